// round 14
// baseline (speedup 1.0000x reference)
#include <cuda_runtime.h>
#include <cuda_bf16.h>
#include <cstdint>

constexpr int Bc = 8;
constexpr int Tc = 2048;
constexpr int Dc = 1024;
constexpr int Hc = 64;

// q/k/v projections (stored tf32-rounded f32)
__device__ float g_q[Bc * Tc * Hc];
__device__ float g_k[Bc * Tc * Hc];
__device__ float g_v[Bc * Tc * Hc];

// tf32-rounded copies of the weights
__device__ float g_wq[Dc * Hc];
__device__ float g_wk[Dc * Hc];
__device__ float g_wv[Dc * Hc];

// split-KV partials: 40 chunk-slots per batch (qtile128 i has ceil((i+1)/4) chunks)
constexpr int SLOTS = 40;
__device__ float g_po[Bc * SLOTS * 128 * 64];
__device__ float g_pm[Bc * SLOTS * 128];
__device__ float g_pl[Bc * SLOTS * 128];

__device__ __forceinline__ uint32_t f2tf32(float x) {
    uint32_t u;
    asm("cvt.rna.tf32.f32 %0, %1;" : "=r"(u) : "f"(x));
    return u;
}
__device__ __forceinline__ float ex2f(float x) {
    float y;
    asm("ex2.approx.ftz.f32 %0, %1;" : "=f"(y) : "f"(x));
    return y;
}
__device__ __forceinline__ void mma_tf32(float* c,
    uint32_t a0, uint32_t a1, uint32_t a2, uint32_t a3,
    uint32_t b0, uint32_t b1)
{
    asm volatile(
        "mma.sync.aligned.m16n8k8.row.col.f32.tf32.tf32.f32 "
        "{%0,%1,%2,%3}, {%4,%5,%6,%7}, {%8,%9}, {%0,%1,%2,%3};"
        : "+f"(c[0]), "+f"(c[1]), "+f"(c[2]), "+f"(c[3])
        : "r"(a0), "r"(a1), "r"(a2), "r"(a3), "r"(b0), "r"(b1));
}
__device__ __forceinline__ void ldsm_x4(
    uint32_t& r0, uint32_t& r1, uint32_t& r2, uint32_t& r3, uint32_t addr)
{
    asm volatile("ldmatrix.sync.aligned.m8n8.x4.shared.b16 {%0,%1,%2,%3}, [%4];"
                 : "=r"(r0), "=r"(r1), "=r"(r2), "=r"(r3) : "r"(addr));
}
__device__ __forceinline__ uint32_t smem_u32(const void* p) {
    return (uint32_t)__cvta_generic_to_shared(p);
}
__device__ __forceinline__ void cpa16(uint32_t dst, const void* src) {
    asm volatile("cp.async.ca.shared.global [%0], [%1], 16;" :: "r"(dst), "l"(src));
}
#define CP_COMMIT() asm volatile("cp.async.commit_group;")

// ---------------------------------------------------------------------------
// W prepass
// ---------------------------------------------------------------------------
__global__ __launch_bounds__(256) void prep_w_kernel(
    const float* __restrict__ Wq, const float* __restrict__ Wk, const float* __restrict__ Wv)
{
    const int idx = blockIdx.x * 256 + threadIdx.x;
    const int p   = idx / (Dc * Hc / 4);
    const int r   = idx % (Dc * Hc / 4);
    const float* src = (p == 0) ? Wq : (p == 1) ? Wk : Wv;
    float* dst = (p == 0) ? g_wq : (p == 1) ? g_wk : g_wv;
    float4 v = *(const float4*)(src + r * 4);
    float4 o = make_float4(__uint_as_float(f2tf32(v.x)), __uint_as_float(f2tf32(v.y)),
                           __uint_as_float(f2tf32(v.z)), __uint_as_float(f2tf32(v.w)));
    *(float4*)(dst + r * 4) = o;
}

// ---------------------------------------------------------------------------
// Fused projection: BM=64, 3-stage cp.async, 2 CTAs/SM, grid 256.
// ---------------------------------------------------------------------------
#define XPAD   36
#define WPAD   72
#define XS_F   (64 * XPAD)
#define STAGEF (XS_F + 3 * 32 * WPAD)       // 9216 floats = 36 KB
#define PSMEM  (3 * STAGEF * 4)             // 110592 bytes

__device__ __forceinline__ void proj_stage_async(
    uint32_t sb, const float* __restrict__ x,
    const float* const* Wp, int m0, int k0, int t)
{
    // x tile [64][32]: 512 chunks
#pragma unroll
    for (int i = 0; i < 2; i++) {
        int idx = t + i * 384;
        if (idx < 512) {
            int row = idx >> 3;
            int c4  = (idx & 7) << 2;
            cpa16(sb + (uint32_t)(row * XPAD + c4) * 4,
                  x + (size_t)(m0 + row) * Dc + k0 + c4);
        }
    }
    // W tiles 3x[32][64]: 1536 chunks
#pragma unroll
    for (int i = 0; i < 4; i++) {
        int idx = t + i * 384;
        int p   = idx >> 9;
        int rem = idx & 511;
        int row = rem >> 4;
        int c4  = (rem & 15) << 2;
        cpa16(sb + (uint32_t)(XS_F + (p * 32 + row) * WPAD + c4) * 4,
              Wp[p] + (size_t)(k0 + row) * Hc + c4);
    }
}

__global__ __launch_bounds__(384, 2) void proj_kernel(
    const float* __restrict__ x,
    const float* __restrict__ bq, const float* __restrict__ bk, const float* __restrict__ bv)
{
    extern __shared__ float psm[];
    const float* Wp[3] = { g_wq, g_wk, g_wv };

    const int t    = threadIdx.x;
    const int w    = t >> 5;
    const int p    = w >> 2;
    const int ww   = w & 3;
    const int lane = t & 31;
    const int g    = lane >> 2;
    const int q4   = lane & 3;
    const int m0   = blockIdx.x * 64;

    const uint32_t sb = smem_u32(psm);

    const int mrow = lane & 7;
    const int msel = lane >> 3;
    const uint32_t a_lane_off = (uint32_t)(((msel & 1) * 8 + mrow) * XPAD + (msel >> 1) * 4) * 4;

    float acc[8][4];
#pragma unroll
    for (int nf = 0; nf < 8; nf++)
#pragma unroll
        for (int j = 0; j < 4; j++) acc[nf][j] = 0.f;

    proj_stage_async(sb,                  x, Wp, m0, 0,  t);
    CP_COMMIT();
    proj_stage_async(sb + STAGEF * 4,     x, Wp, m0, 32, t);
    CP_COMMIT();

    for (int it = 0; it < 32; it++) {
        if (it < 30) {
            proj_stage_async(sb + (uint32_t)((it + 2) % 3) * STAGEF * 4,
                             x, Wp, m0, (it + 2) * 32, t);
            CP_COMMIT();
            asm volatile("cp.async.wait_group 2;");
        } else if (it == 30) {
            asm volatile("cp.async.wait_group 1;");
        } else {
            asm volatile("cp.async.wait_group 0;");
        }
        __syncthreads();

        const uint32_t sXs = sb + (uint32_t)(it % 3) * STAGEF * 4;
        const float* Ws = psm + (it % 3) * STAGEF + XS_F + p * 32 * WPAD;

#pragma unroll
        for (int ks = 0; ks < 4; ks++) {
            const int kc = ks * 8 + q4;
            uint32_t addr = sXs + a_lane_off + (uint32_t)(ww * 16 * XPAD + ks * 8) * 4;
            uint32_t r0, r1, r2, r3;
            ldsm_x4(r0, r1, r2, r3, addr);
            uint32_t a0 = f2tf32(__uint_as_float(r0));
            uint32_t a1 = f2tf32(__uint_as_float(r1));
            uint32_t a2 = f2tf32(__uint_as_float(r2));
            uint32_t a3 = f2tf32(__uint_as_float(r3));
#pragma unroll
            for (int nf = 0; nf < 8; nf++) {
                uint32_t b0 = __float_as_uint(Ws[(kc    ) * WPAD + nf * 8 + g]);
                uint32_t b1 = __float_as_uint(Ws[(kc + 4) * WPAD + nf * 8 + g]);
                mma_tf32(acc[nf], a0, a1, a2, a3, b0, b1);
            }
        }
        __syncthreads();
    }

    const float* biases[3] = { bq, bk, bv };
    float* outs[3] = { g_q, g_k, g_v };
    float* out = outs[p];
    const float* bias = biases[p];
    const int r0 = m0 + ww * 16 + g;
#pragma unroll
    for (int nf = 0; nf < 8; nf++) {
        int col = nf * 8 + 2 * q4;
        float b0 = bias[col], b1 = bias[col + 1];
        float2 v0 = make_float2(__uint_as_float(f2tf32(acc[nf][0] + b0)),
                                __uint_as_float(f2tf32(acc[nf][1] + b1)));
        float2 v1 = make_float2(__uint_as_float(f2tf32(acc[nf][2] + b0)),
                                __uint_as_float(f2tf32(acc[nf][3] + b1)));
        *(float2*)(out + (size_t)r0 * Hc + col)       = v0;
        *(float2*)(out + (size_t)(r0 + 8) * Hc + col) = v1;
    }
}

// ---------------------------------------------------------------------------
// Attention partials: 128-query blocks, 8 warps, shared K/V staging (2x reuse),
// cp.async 2-stage, LDSM K frags, shuffle PV A-frags. qt<4 writes directly.
// ---------------------------------------------------------------------------
#define KPAD 68
#define VPAD 72
#define KTILE (64 * KPAD)
#define VTILE (64 * VPAD)
#define STF   (KTILE + VTILE)
#define ASMEM (2 * STF * 4)   // 71680 bytes

__device__ __forceinline__ void attn_stage_async(
    uint32_t sb, const float* __restrict__ kb, const float* __restrict__ vb,
    int kn0, int t)
{
#pragma unroll
    for (int i = 0; i < 4; i++) {
        int idx = t + i * 256;
        int row = idx >> 4;
        int c4  = (idx & 15) << 2;
        cpa16(sb + (uint32_t)(row * KPAD + c4) * 4,
              kb + (size_t)(kn0 + row) * Hc + c4);
    }
#pragma unroll
    for (int i = 0; i < 4; i++) {
        int idx = t + i * 256;
        int row = idx >> 4;
        int c4  = (idx & 15) << 2;
        cpa16(sb + (uint32_t)(KTILE + row * VPAD + c4) * 4,
              vb + (size_t)(kn0 + row) * Hc + c4);
    }
}

__global__ __launch_bounds__(256, 2) void attn_partial_kernel(float* __restrict__ gout)
{
    extern __shared__ float sm[];
    const uint32_t sb = smem_u32(sm);

    const int b   = blockIdx.y;
    const int idx = (int)(gridDim.x - 1 - blockIdx.x);   // heavy chunks first

    // decode (qtile128, chunk): group gg has qtiles 4gg..4gg+3, gg+1 chunks each
    int qt = 0, ch = 0;
#pragma unroll
    for (int gg = 3; gg >= 0; gg--) {
        int s = 2 * gg * (gg + 1);
        if (idx >= s) { qt = 4 * gg + (idx - s) / (gg + 1); ch = (idx - s) % (gg + 1); break; }
    }
    const int q0  = qt * 128;
    const int kt0 = ch * 8;
    const int kt1 = min(kt0 + 8, 2 * qt + 2);

    const int t    = threadIdx.x;
    const int w    = t >> 5;       // 0..7: q rows w*16 .. w*16+15
    const int lane = t & 31;
    const int g    = lane >> 2;
    const int q4   = lane & 3;

    const int mrow = lane & 7;
    const int msel = lane >> 3;
    const uint32_t k_lane_off = (uint32_t)(mrow * KPAD + msel * 4) * 4;

    const float* qb = g_q + (size_t)b * Tc * Hc;
    const float* kb = g_k + (size_t)b * Tc * Hc;
    const float* vb = g_v + (size_t)b * Tc * Hc;

    attn_stage_async(sb, kb, vb, kt0 * 64, t);
    CP_COMMIT();

    const float SC = 0.125f * 1.44269504f;
    uint32_t qa[8][4];
    {
        const float* r0 = qb + (size_t)(q0 + w * 16 + g) * Hc;
        const float* r1 = r0 + 8 * Hc;
#pragma unroll
        for (int ks = 0; ks < 8; ks++) {
            qa[ks][0] = f2tf32(r0[ks * 8 + q4] * SC);
            qa[ks][1] = f2tf32(r1[ks * 8 + q4] * SC);
            qa[ks][2] = f2tf32(r0[ks * 8 + q4 + 4] * SC);
            qa[ks][3] = f2tf32(r1[ks * 8 + q4 + 4] * SC);
        }
    }

    float o[8][4];
#pragma unroll
    for (int nf = 0; nf < 8; nf++)
#pragma unroll
        for (int j = 0; j < 4; j++) o[nf][j] = 0.f;
    float m0 = -1e30f, m1 = -1e30f, l0 = 0.f, l1 = 0.f;

    const int srcA = 4 * g + (q4 >> 1);
    const int srcB = srcA + 2;
    const bool odd = (q4 & 1);

    for (int kt = kt0; kt < kt1; kt++) {
        const int buf = (kt - kt0) & 1;
        if (kt + 1 < kt1) {
            attn_stage_async(sb + (uint32_t)(buf ^ 1) * STF * 4, kb, vb, (kt + 1) * 64, t);
            CP_COMMIT();
            asm volatile("cp.async.wait_group 1;");
        } else {
            asm volatile("cp.async.wait_group 0;");
        }
        __syncthreads();

        const uint32_t sKs = sb + (uint32_t)buf * STF * 4;
        const float* Vs = sm + buf * STF + KTILE;
        const int kn0 = kt * 64;

        // S = Q @ K^T
        float sf[8][4];
#pragma unroll
        for (int nf = 0; nf < 8; nf++)
            sf[nf][0] = sf[nf][1] = sf[nf][2] = sf[nf][3] = 0.f;

#pragma unroll
        for (int ks2 = 0; ks2 < 4; ks2++) {
#pragma unroll
            for (int nf = 0; nf < 8; nf++) {
                uint32_t addr = sKs + k_lane_off + (uint32_t)(nf * 8 * KPAD + ks2 * 16) * 4;
                uint32_t b0, b1, b2, b3;
                ldsm_x4(b0, b1, b2, b3, addr);
                mma_tf32(sf[nf], qa[2 * ks2][0], qa[2 * ks2][1], qa[2 * ks2][2], qa[2 * ks2][3], b0, b1);
                mma_tf32(sf[nf], qa[2 * ks2 + 1][0], qa[2 * ks2 + 1][1], qa[2 * ks2 + 1][2], qa[2 * ks2 + 1][3], b2, b3);
            }
        }

        // causal mask: needed only where the kv tile can exceed this warp's rows
        if (kn0 + 63 > q0 + w * 16) {
            const int r0 = q0 + w * 16 + g;
            const int r1 = r0 + 8;
#pragma unroll
            for (int nf = 0; nf < 8; nf++) {
                int c0 = kn0 + nf * 8 + 2 * q4;
                if (c0     > r0) sf[nf][0] = -1e30f;
                if (c0 + 1 > r0) sf[nf][1] = -1e30f;
                if (c0     > r1) sf[nf][2] = -1e30f;
                if (c0 + 1 > r1) sf[nf][3] = -1e30f;
            }
        }

        float mx0 = -1e30f, mx1 = -1e30f;
#pragma unroll
        for (int nf = 0; nf < 8; nf++) {
            mx0 = fmaxf(mx0, fmaxf(sf[nf][0], sf[nf][1]));
            mx1 = fmaxf(mx1, fmaxf(sf[nf][2], sf[nf][3]));
        }
        mx0 = fmaxf(mx0, __shfl_xor_sync(0xffffffffu, mx0, 1));
        mx0 = fmaxf(mx0, __shfl_xor_sync(0xffffffffu, mx0, 2));
        mx1 = fmaxf(mx1, __shfl_xor_sync(0xffffffffu, mx1, 1));
        mx1 = fmaxf(mx1, __shfl_xor_sync(0xffffffffu, mx1, 2));

        float mn0 = fmaxf(m0, mx0), mn1 = fmaxf(m1, mx1);
        float sc0 = ex2f(m0 - mn0), sc1 = ex2f(m1 - mn1);

        float rs0 = 0.f, rs1 = 0.f;
#pragma unroll
        for (int nf = 0; nf < 8; nf++) {
            sf[nf][0] = ex2f(sf[nf][0] - mn0);
            sf[nf][1] = ex2f(sf[nf][1] - mn0);
            sf[nf][2] = ex2f(sf[nf][2] - mn1);
            sf[nf][3] = ex2f(sf[nf][3] - mn1);
            rs0 += sf[nf][0] + sf[nf][1];
            rs1 += sf[nf][2] + sf[nf][3];
        }
        rs0 += __shfl_xor_sync(0xffffffffu, rs0, 1);
        rs0 += __shfl_xor_sync(0xffffffffu, rs0, 2);
        rs1 += __shfl_xor_sync(0xffffffffu, rs1, 1);
        rs1 += __shfl_xor_sync(0xffffffffu, rs1, 2);

        l0 = l0 * sc0 + rs0;  m0 = mn0;
        l1 = l1 * sc1 + rs1;  m1 = mn1;
#pragma unroll
        for (int nf = 0; nf < 8; nf++) {
            o[nf][0] *= sc0;  o[nf][1] *= sc0;
            o[nf][2] *= sc1;  o[nf][3] *= sc1;
        }

        // O += P @ V (P via shuffles; V raw scalar LDS)
#pragma unroll
        for (int ks = 0; ks < 8; ks++) {
            float s0A = __shfl_sync(0xffffffffu, sf[ks][0], srcA);
            float s1A = __shfl_sync(0xffffffffu, sf[ks][1], srcA);
            float s2A = __shfl_sync(0xffffffffu, sf[ks][2], srcA);
            float s3A = __shfl_sync(0xffffffffu, sf[ks][3], srcA);
            float s0B = __shfl_sync(0xffffffffu, sf[ks][0], srcB);
            float s1B = __shfl_sync(0xffffffffu, sf[ks][1], srcB);
            float s2B = __shfl_sync(0xffffffffu, sf[ks][2], srcB);
            float s3B = __shfl_sync(0xffffffffu, sf[ks][3], srcB);
            uint32_t a0 = f2tf32(odd ? s1A : s0A);
            uint32_t a1 = f2tf32(odd ? s3A : s2A);
            uint32_t a2 = f2tf32(odd ? s1B : s0B);
            uint32_t a3 = f2tf32(odd ? s3B : s2B);
#pragma unroll
            for (int nf = 0; nf < 8; nf++) {
                uint32_t b0 = __float_as_uint(Vs[(ks * 8 + q4    ) * VPAD + nf * 8 + g]);
                uint32_t b1 = __float_as_uint(Vs[(ks * 8 + q4 + 4) * VPAD + nf * 8 + g]);
                mma_tf32(o[nf], a0, a1, a2, a3, b0, b1);
            }
        }
        __syncthreads();
    }

    const int r0 = w * 16 + g;
    const int r1 = r0 + 8;

    if (qt < 4) {
        // single chunk covers the whole causal history: write final output
        float inv0 = 1.f / l0, inv1 = 1.f / l1;
        float* po = gout + ((size_t)b * Tc + q0) * Hc;
#pragma unroll
        for (int nf = 0; nf < 8; nf++) {
            int col = nf * 8 + 2 * q4;
            *(float2*)(po + (size_t)r0 * Hc + col) = make_float2(o[nf][0] * inv0, o[nf][1] * inv0);
            *(float2*)(po + (size_t)r1 * Hc + col) = make_float2(o[nf][2] * inv1, o[nf][3] * inv1);
        }
    } else {
        const int slot = b * SLOTS + idx;
        float* po = g_po + (size_t)slot * (128 * 64);
#pragma unroll
        for (int nf = 0; nf < 8; nf++) {
            int col = nf * 8 + 2 * q4;
            *(float2*)(po + r0 * 64 + col) = make_float2(o[nf][0], o[nf][1]);
            *(float2*)(po + r1 * 64 + col) = make_float2(o[nf][2], o[nf][3]);
        }
        if (q4 == 0) {
            g_pm[slot * 128 + r0] = m0;  g_pm[slot * 128 + r1] = m1;
            g_pl[slot * 128 + r0] = l0;  g_pl[slot * 128 + r1] = l1;
        }
    }
}

// ---------------------------------------------------------------------------
// Merge: combine <=4 partials per row; qt<4 rows written directly by attn.
// ---------------------------------------------------------------------------
__global__ __launch_bounds__(256) void merge_kernel(float* __restrict__ out)
{
    const int gid  = blockIdx.x * 8 + (threadIdx.x >> 5);
    const int lane = threadIdx.x & 31;
    const int b = gid >> 11;
    const int q = gid & 2047;
    const int qt    = q >> 7;           // qtile128
    if (qt < 4) return;                 // written directly by attn_partial
    const int rowin = q & 127;
    const int gg    = qt >> 2;
    const int nch   = gg + 1;
    const int base  = b * SLOTS + 2 * gg * (gg + 1) + (qt - 4 * gg) * (gg + 1);

    float mv[4];
    float M = -1e30f;
    for (int c = 0; c < nch; c++) {
        mv[c] = g_pm[(base + c) * 128 + rowin];
        M = fmaxf(M, mv[c]);
    }
    float L = 0.f, o0 = 0.f, o1 = 0.f;
    const int col = lane * 2;
    for (int c = 0; c < nch; c++) {
        float wgt = ex2f(mv[c] - M);
        L += wgt * g_pl[(base + c) * 128 + rowin];
        float2 ov = *(const float2*)(g_po + ((size_t)(base + c) * 128 + rowin) * 64 + col);
        o0 += wgt * ov.x;
        o1 += wgt * ov.y;
    }
    float inv = 1.f / L;
    *(float2*)(out + ((size_t)b * Tc + q) * Hc + col) = make_float2(o0 * inv, o1 * inv);
}

// ---------------------------------------------------------------------------
extern "C" void kernel_launch(void* const* d_in, const int* in_sizes, int n_in,
                              void* d_out, int out_size)
{
    (void)in_sizes; (void)n_in; (void)out_size;
    const float* x  = (const float*)d_in[0];
    const float* Wk = (const float*)d_in[1];
    const float* bk = (const float*)d_in[2];
    const float* Wq = (const float*)d_in[3];
    const float* bq = (const float*)d_in[4];
    const float* Wv = (const float*)d_in[5];
    const float* bv = (const float*)d_in[6];
    float* out = (float*)d_out;

    cudaFuncSetAttribute(proj_kernel, cudaFuncAttributeMaxDynamicSharedMemorySize, PSMEM);
    cudaFuncSetAttribute(attn_partial_kernel, cudaFuncAttributeMaxDynamicSharedMemorySize, ASMEM);

    prep_w_kernel<<<(3 * Dc * Hc / 4) / 256, 256>>>(Wq, Wk, Wv);

    proj_kernel<<<(Bc * Tc) / 64, 384, PSMEM>>>(x, bq, bk, bv);

    dim3 ag(SLOTS, Bc);
    attn_partial_kernel<<<ag, 256, ASMEM>>>(out);

    merge_kernel<<<(Bc * Tc) / 8, 256>>>(out);
}

// round 15
// speedup vs baseline: 1.2510x; 1.2510x over previous
#include <cuda_runtime.h>
#include <cuda_bf16.h>
#include <cstdint>

constexpr int Bc = 8;
constexpr int Tc = 2048;
constexpr int Dc = 1024;
constexpr int Hc = 64;

// q/k/v projections (stored tf32-rounded f32)
__device__ float g_q[Bc * Tc * Hc];
__device__ float g_k[Bc * Tc * Hc];
__device__ float g_v[Bc * Tc * Hc];

// tf32-rounded copies of the weights
__device__ float g_wq[Dc * Hc];
__device__ float g_wk[Dc * Hc];
__device__ float g_wv[Dc * Hc];

// split-KV partials: chunk = 4 KV tiles. qtile i (of 32) has ceil((i+1)/4)
// chunks; per batch = 144 slots. group gg: qtiles 4gg..4gg+3, gg+1 chunks each.
constexpr int SLOTS = 144;
__device__ float g_po[Bc * SLOTS * 64 * 64];   // unnormalized O
__device__ float g_pm[Bc * SLOTS * 64];        // row max (exp2 space)
__device__ float g_pl[Bc * SLOTS * 64];        // row sum

__device__ __forceinline__ uint32_t f2tf32(float x) {
    uint32_t u;
    asm("cvt.rna.tf32.f32 %0, %1;" : "=r"(u) : "f"(x));
    return u;
}
__device__ __forceinline__ float ex2f(float x) {
    float y;
    asm("ex2.approx.ftz.f32 %0, %1;" : "=f"(y) : "f"(x));
    return y;
}
__device__ __forceinline__ void mma_tf32(float* c,
    uint32_t a0, uint32_t a1, uint32_t a2, uint32_t a3,
    uint32_t b0, uint32_t b1)
{
    asm volatile(
        "mma.sync.aligned.m16n8k8.row.col.f32.tf32.tf32.f32 "
        "{%0,%1,%2,%3}, {%4,%5,%6,%7}, {%8,%9}, {%0,%1,%2,%3};"
        : "+f"(c[0]), "+f"(c[1]), "+f"(c[2]), "+f"(c[3])
        : "r"(a0), "r"(a1), "r"(a2), "r"(a3), "r"(b0), "r"(b1));
}
__device__ __forceinline__ uint32_t smem_u32(const void* p) {
    return (uint32_t)__cvta_generic_to_shared(p);
}
__device__ __forceinline__ void cpa16(uint32_t dst, const void* src) {
    asm volatile("cp.async.ca.shared.global [%0], [%1], 16;" :: "r"(dst), "l"(src));
}
#define CP_COMMIT() asm volatile("cp.async.commit_group;")

// ---------------------------------------------------------------------------
// W prepass: tf32-round the three weight matrices into scratch.
// ---------------------------------------------------------------------------
__global__ __launch_bounds__(256) void prep_w_kernel(
    const float* __restrict__ Wq, const float* __restrict__ Wk, const float* __restrict__ Wv)
{
    const int idx = blockIdx.x * 256 + threadIdx.x;
    const int p   = idx / (Dc * Hc / 4);
    const int r   = idx % (Dc * Hc / 4);
    const float* src = (p == 0) ? Wq : (p == 1) ? Wk : Wv;
    float* dst = (p == 0) ? g_wq : (p == 1) ? g_wk : g_wv;
    float4 v = *(const float4*)(src + r * 4);
    float4 o = make_float4(__uint_as_float(f2tf32(v.x)), __uint_as_float(f2tf32(v.y)),
                           __uint_as_float(f2tf32(v.z)), __uint_as_float(f2tf32(v.w)));
    *(float4*)(dst + r * 4) = o;
}

// ---------------------------------------------------------------------------
// Fused projection (round-12 form: BM=128, 3-stage cp.async, raw B frags,
// cvt-at-A-fragment-load, tf32-rounded epilogue).
// ---------------------------------------------------------------------------
#define XPAD   36
#define WPAD   72
#define XS_F   (128 * XPAD)
#define STAGEF (XS_F + 3 * 32 * WPAD)
#define PSTAGES 3
#define PSMEM  (PSTAGES * STAGEF * 4)

__device__ __forceinline__ void proj_stage_async(
    uint32_t sb, const float* __restrict__ x,
    const float* const* Wp, int m0, int k0, int t)
{
    for (int idx = t; idx < 1024; idx += 384) {
        int row = idx >> 3;
        int c4  = (idx & 7) << 2;
        cpa16(sb + (uint32_t)(row * XPAD + c4) * 4,
              x + (size_t)(m0 + row) * Dc + k0 + c4);
    }
#pragma unroll
    for (int i = 0; i < 4; i++) {
        int idx = t + i * 384;
        int p   = idx >> 9;
        int rem = idx & 511;
        int row = rem >> 4;
        int c4  = (rem & 15) << 2;
        cpa16(sb + (uint32_t)(XS_F + (p * 32 + row) * WPAD + c4) * 4,
              Wp[p] + (size_t)(k0 + row) * Hc + c4);
    }
}

__global__ __launch_bounds__(384, 1) void proj_kernel(
    const float* __restrict__ x,
    const float* __restrict__ bq, const float* __restrict__ bk, const float* __restrict__ bv)
{
    extern __shared__ float psm[];
    const float* Wp[3] = { g_wq, g_wk, g_wv };

    const int t    = threadIdx.x;
    const int w    = t >> 5;
    const int p    = w >> 2;
    const int ww   = w & 3;
    const int lane = t & 31;
    const int g    = lane >> 2;
    const int q4   = lane & 3;
    const int m0   = blockIdx.x * 128;

    const uint32_t sb = smem_u32(psm);

    float acc[2][8][4];
#pragma unroll
    for (int i = 0; i < 2; i++)
#pragma unroll
        for (int nf = 0; nf < 8; nf++)
#pragma unroll
            for (int j = 0; j < 4; j++) acc[i][nf][j] = 0.f;

    proj_stage_async(sb,              x, Wp, m0, 0,  t);
    CP_COMMIT();
    proj_stage_async(sb + STAGEF * 4, x, Wp, m0, 32, t);
    CP_COMMIT();

    for (int it = 0; it < 32; it++) {
        if (it < 30) {
            proj_stage_async(sb + (uint32_t)((it + 2) % 3) * STAGEF * 4,
                             x, Wp, m0, (it + 2) * 32, t);
            CP_COMMIT();
            asm volatile("cp.async.wait_group 2;");
        } else if (it == 30) {
            asm volatile("cp.async.wait_group 1;");
        } else {
            asm volatile("cp.async.wait_group 0;");
        }
        __syncthreads();

        const float* Xs = psm + (it % 3) * STAGEF;
        const float* Ws = Xs + XS_F + p * 32 * WPAD;

#pragma unroll
        for (int ks = 0; ks < 4; ks++) {
            const int kc = ks * 8 + q4;
            uint32_t a[2][4];
#pragma unroll
            for (int i = 0; i < 2; i++) {
                const int r = ww * 32 + i * 16 + g;
                a[i][0] = f2tf32(Xs[(r    ) * XPAD + kc]);
                a[i][1] = f2tf32(Xs[(r + 8) * XPAD + kc]);
                a[i][2] = f2tf32(Xs[(r    ) * XPAD + kc + 4]);
                a[i][3] = f2tf32(Xs[(r + 8) * XPAD + kc + 4]);
            }
#pragma unroll
            for (int nf = 0; nf < 8; nf++) {
                uint32_t b0 = __float_as_uint(Ws[(kc    ) * WPAD + nf * 8 + g]);
                uint32_t b1 = __float_as_uint(Ws[(kc + 4) * WPAD + nf * 8 + g]);
                mma_tf32(acc[0][nf], a[0][0], a[0][1], a[0][2], a[0][3], b0, b1);
                mma_tf32(acc[1][nf], a[1][0], a[1][1], a[1][2], a[1][3], b0, b1);
            }
        }
        __syncthreads();
    }

    const float* biases[3] = { bq, bk, bv };
    float* outs[3] = { g_q, g_k, g_v };
    float* out = outs[p];
    const float* bias = biases[p];
#pragma unroll
    for (int i = 0; i < 2; i++) {
        const int r0 = m0 + ww * 32 + i * 16 + g;
#pragma unroll
        for (int nf = 0; nf < 8; nf++) {
            int col = nf * 8 + 2 * q4;
            float b0 = bias[col], b1 = bias[col + 1];
            float2 v0 = make_float2(__uint_as_float(f2tf32(acc[i][nf][0] + b0)),
                                    __uint_as_float(f2tf32(acc[i][nf][1] + b1)));
            float2 v1 = make_float2(__uint_as_float(f2tf32(acc[i][nf][2] + b0)),
                                    __uint_as_float(f2tf32(acc[i][nf][3] + b1)));
            *(float2*)(out + (size_t)r0 * Hc + col)       = v0;
            *(float2*)(out + (size_t)(r0 + 8) * Hc + col) = v1;
        }
    }
}

// ---------------------------------------------------------------------------
// Attention partials (round-12 form; chunk = 4 KV tiles for wave packing).
// 64-query blocks, 4 warps, cp.async 2-stage, raw K/V frags, shuffle PV.
// qt<4 (single chunk) writes normalized output directly.
// ---------------------------------------------------------------------------
#define KPAD 68
#define VPAD 72
#define KTILE (64 * KPAD)
#define VTILE (64 * VPAD)
#define STF   (KTILE + VTILE)
#define ASMEM (2 * STF * 4)

__device__ __forceinline__ void attn_stage_async(
    uint32_t sb, const float* __restrict__ kb, const float* __restrict__ vb,
    int kn0, int t)
{
#pragma unroll
    for (int i = 0; i < 8; i++) {
        int idx = t + i * 128;
        int row = idx >> 4;
        int c4  = (idx & 15) << 2;
        cpa16(sb + (uint32_t)(row * KPAD + c4) * 4,
              kb + (size_t)(kn0 + row) * Hc + c4);
    }
#pragma unroll
    for (int i = 0; i < 8; i++) {
        int idx = t + i * 128;
        int row = idx >> 4;
        int c4  = (idx & 15) << 2;
        cpa16(sb + (uint32_t)(KTILE + row * VPAD + c4) * 4,
              vb + (size_t)(kn0 + row) * Hc + c4);
    }
}

__global__ __launch_bounds__(128) void attn_partial_kernel(float* __restrict__ gout)
{
    extern __shared__ float sm[];
    const uint32_t sb = smem_u32(sm);

    const int b   = blockIdx.y;
    const int idx = (int)(gridDim.x - 1 - blockIdx.x);   // heavy chunks first

    // decode (qtile, chunk): group gg (0..7) -> qtiles 4gg..4gg+3, gg+1 chunks
    int qt = 0, ch = 0;
#pragma unroll
    for (int gg = 7; gg >= 0; gg--) {
        int s = 2 * gg * (gg + 1);
        if (idx >= s) { qt = 4 * gg + (idx - s) / (gg + 1); ch = (idx - s) % (gg + 1); break; }
    }
    const int q0  = qt * 64;
    const int kt0 = ch * 4;
    const int kt1 = min(kt0 + 4, qt + 1);

    const int t    = threadIdx.x;
    const int w    = t >> 5;
    const int lane = t & 31;
    const int g    = lane >> 2;
    const int q4   = lane & 3;

    const float* qb = g_q + (size_t)b * Tc * Hc;
    const float* kb = g_k + (size_t)b * Tc * Hc;
    const float* vb = g_v + (size_t)b * Tc * Hc;

    attn_stage_async(sb, kb, vb, kt0 * 64, t);
    CP_COMMIT();

    const float SC = 0.125f * 1.44269504f;
    uint32_t qa[8][4];
    {
        const float* r0 = qb + (size_t)(q0 + w * 16 + g) * Hc;
        const float* r1 = r0 + 8 * Hc;
#pragma unroll
        for (int ks = 0; ks < 8; ks++) {
            qa[ks][0] = f2tf32(r0[ks * 8 + q4] * SC);
            qa[ks][1] = f2tf32(r1[ks * 8 + q4] * SC);
            qa[ks][2] = f2tf32(r0[ks * 8 + q4 + 4] * SC);
            qa[ks][3] = f2tf32(r1[ks * 8 + q4 + 4] * SC);
        }
    }

    float o[8][4];
#pragma unroll
    for (int nf = 0; nf < 8; nf++)
#pragma unroll
        for (int j = 0; j < 4; j++) o[nf][j] = 0.f;
    float m0 = -1e30f, m1 = -1e30f, l0 = 0.f, l1 = 0.f;

    const int srcA = 4 * g + (q4 >> 1);
    const int srcB = srcA + 2;
    const bool odd = (q4 & 1);

    for (int kt = kt0; kt < kt1; kt++) {
        const int buf = (kt - kt0) & 1;
        if (kt + 1 < kt1) {
            attn_stage_async(sb + (uint32_t)(buf ^ 1) * STF * 4, kb, vb, (kt + 1) * 64, t);
            CP_COMMIT();
            asm volatile("cp.async.wait_group 1;");
        } else {
            asm volatile("cp.async.wait_group 0;");
        }
        __syncthreads();

        const float* Ks = sm + buf * STF;
        const float* Vs = Ks + KTILE;
        const int kn0 = kt * 64;

        // S = Q @ K^T  (K fragments raw: values pre-rounded by proj)
        float sf[8][4];
#pragma unroll
        for (int nf = 0; nf < 8; nf++) {
            sf[nf][0] = sf[nf][1] = sf[nf][2] = sf[nf][3] = 0.f;
#pragma unroll
            for (int ks = 0; ks < 8; ks++) {
                uint32_t b0 = __float_as_uint(Ks[(nf * 8 + g) * KPAD + ks * 8 + q4]);
                uint32_t b1 = __float_as_uint(Ks[(nf * 8 + g) * KPAD + ks * 8 + q4 + 4]);
                mma_tf32(sf[nf], qa[ks][0], qa[ks][1], qa[ks][2], qa[ks][3], b0, b1);
            }
        }

        if (kt == qt) {
            const int r0 = q0 + w * 16 + g;
            const int r1 = r0 + 8;
#pragma unroll
            for (int nf = 0; nf < 8; nf++) {
                int c0 = kn0 + nf * 8 + 2 * q4;
                if (c0     > r0) sf[nf][0] = -1e30f;
                if (c0 + 1 > r0) sf[nf][1] = -1e30f;
                if (c0     > r1) sf[nf][2] = -1e30f;
                if (c0 + 1 > r1) sf[nf][3] = -1e30f;
            }
        }

        float mx0 = -1e30f, mx1 = -1e30f;
#pragma unroll
        for (int nf = 0; nf < 8; nf++) {
            mx0 = fmaxf(mx0, fmaxf(sf[nf][0], sf[nf][1]));
            mx1 = fmaxf(mx1, fmaxf(sf[nf][2], sf[nf][3]));
        }
        mx0 = fmaxf(mx0, __shfl_xor_sync(0xffffffffu, mx0, 1));
        mx0 = fmaxf(mx0, __shfl_xor_sync(0xffffffffu, mx0, 2));
        mx1 = fmaxf(mx1, __shfl_xor_sync(0xffffffffu, mx1, 1));
        mx1 = fmaxf(mx1, __shfl_xor_sync(0xffffffffu, mx1, 2));

        float mn0 = fmaxf(m0, mx0), mn1 = fmaxf(m1, mx1);
        float sc0 = ex2f(m0 - mn0), sc1 = ex2f(m1 - mn1);

        float rs0 = 0.f, rs1 = 0.f;
#pragma unroll
        for (int nf = 0; nf < 8; nf++) {
            sf[nf][0] = ex2f(sf[nf][0] - mn0);
            sf[nf][1] = ex2f(sf[nf][1] - mn0);
            sf[nf][2] = ex2f(sf[nf][2] - mn1);
            sf[nf][3] = ex2f(sf[nf][3] - mn1);
            rs0 += sf[nf][0] + sf[nf][1];
            rs1 += sf[nf][2] + sf[nf][3];
        }
        rs0 += __shfl_xor_sync(0xffffffffu, rs0, 1);
        rs0 += __shfl_xor_sync(0xffffffffu, rs0, 2);
        rs1 += __shfl_xor_sync(0xffffffffu, rs1, 1);
        rs1 += __shfl_xor_sync(0xffffffffu, rs1, 2);

        l0 = l0 * sc0 + rs0;  m0 = mn0;
        l1 = l1 * sc1 + rs1;  m1 = mn1;
#pragma unroll
        for (int nf = 0; nf < 8; nf++) {
            o[nf][0] *= sc0;  o[nf][1] *= sc0;
            o[nf][2] *= sc1;  o[nf][3] *= sc1;
        }

        // O += P @ V (P via shuffles; V fragments raw)
#pragma unroll
        for (int ks = 0; ks < 8; ks++) {
            float s0A = __shfl_sync(0xffffffffu, sf[ks][0], srcA);
            float s1A = __shfl_sync(0xffffffffu, sf[ks][1], srcA);
            float s2A = __shfl_sync(0xffffffffu, sf[ks][2], srcA);
            float s3A = __shfl_sync(0xffffffffu, sf[ks][3], srcA);
            float s0B = __shfl_sync(0xffffffffu, sf[ks][0], srcB);
            float s1B = __shfl_sync(0xffffffffu, sf[ks][1], srcB);
            float s2B = __shfl_sync(0xffffffffu, sf[ks][2], srcB);
            float s3B = __shfl_sync(0xffffffffu, sf[ks][3], srcB);
            uint32_t a0 = f2tf32(odd ? s1A : s0A);
            uint32_t a1 = f2tf32(odd ? s3A : s2A);
            uint32_t a2 = f2tf32(odd ? s1B : s0B);
            uint32_t a3 = f2tf32(odd ? s3B : s2B);
#pragma unroll
            for (int nf = 0; nf < 8; nf++) {
                uint32_t b0 = __float_as_uint(Vs[(ks * 8 + q4    ) * VPAD + nf * 8 + g]);
                uint32_t b1 = __float_as_uint(Vs[(ks * 8 + q4 + 4) * VPAD + nf * 8 + g]);
                mma_tf32(o[nf], a0, a1, a2, a3, b0, b1);
            }
        }
        __syncthreads();
    }

    const int r0 = w * 16 + g;
    const int r1 = r0 + 8;

    if (qt < 4) {
        // single chunk covers the whole causal history: write final output
        float inv0 = 1.f / l0, inv1 = 1.f / l1;
        float* po = gout + ((size_t)b * Tc + q0) * Hc;
#pragma unroll
        for (int nf = 0; nf < 8; nf++) {
            int col = nf * 8 + 2 * q4;
            *(float2*)(po + (size_t)r0 * Hc + col) = make_float2(o[nf][0] * inv0, o[nf][1] * inv0);
            *(float2*)(po + (size_t)r1 * Hc + col) = make_float2(o[nf][2] * inv1, o[nf][3] * inv1);
        }
    } else {
        const int slot = b * SLOTS + idx;
        float* po = g_po + (size_t)slot * 4096;
#pragma unroll
        for (int nf = 0; nf < 8; nf++) {
            int col = nf * 8 + 2 * q4;
            *(float2*)(po + r0 * 64 + col) = make_float2(o[nf][0], o[nf][1]);
            *(float2*)(po + r1 * 64 + col) = make_float2(o[nf][2], o[nf][3]);
        }
        if (q4 == 0) {
            g_pm[slot * 64 + r0] = m0;  g_pm[slot * 64 + r1] = m1;
            g_pl[slot * 64 + r0] = l0;  g_pl[slot * 64 + r1] = l1;
        }
    }
}

// ---------------------------------------------------------------------------
// Merge: combine <=8 partials per row; qt<4 rows written directly by attn.
// ---------------------------------------------------------------------------
__global__ __launch_bounds__(256) void merge_kernel(float* __restrict__ out)
{
    const int gid  = blockIdx.x * 8 + (threadIdx.x >> 5);
    const int lane = threadIdx.x & 31;
    const int b = gid >> 11;
    const int q = gid & 2047;
    const int qt    = q >> 6;
    if (qt < 4) return;                 // written directly by attn_partial
    const int rowin = q & 63;
    const int gg    = qt >> 2;
    const int nch   = gg + 1;
    const int base  = b * SLOTS + 2 * gg * (gg + 1) + (qt - 4 * gg) * (gg + 1);

    float mv[8];
    float M = -1e30f;
    for (int c = 0; c < nch; c++) {
        mv[c] = g_pm[(base + c) * 64 + rowin];
        M = fmaxf(M, mv[c]);
    }
    float L = 0.f, o0 = 0.f, o1 = 0.f;
    const int col = lane * 2;
    for (int c = 0; c < nch; c++) {
        float wgt = ex2f(mv[c] - M);
        L += wgt * g_pl[(base + c) * 64 + rowin];
        float2 ov = *(const float2*)(g_po + ((size_t)(base + c) * 64 + rowin) * 64 + col);
        o0 += wgt * ov.x;
        o1 += wgt * ov.y;
    }
    float inv = 1.f / L;
    *(float2*)(out + ((size_t)b * Tc + q) * Hc + col) = make_float2(o0 * inv, o1 * inv);
}

// ---------------------------------------------------------------------------
extern "C" void kernel_launch(void* const* d_in, const int* in_sizes, int n_in,
                              void* d_out, int out_size)
{
    (void)in_sizes; (void)n_in; (void)out_size;
    const float* x  = (const float*)d_in[0];
    const float* Wk = (const float*)d_in[1];
    const float* bk = (const float*)d_in[2];
    const float* Wq = (const float*)d_in[3];
    const float* bq = (const float*)d_in[4];
    const float* Wv = (const float*)d_in[5];
    const float* bv = (const float*)d_in[6];
    float* out = (float*)d_out;

    cudaFuncSetAttribute(proj_kernel, cudaFuncAttributeMaxDynamicSharedMemorySize, PSMEM);
    cudaFuncSetAttribute(attn_partial_kernel, cudaFuncAttributeMaxDynamicSharedMemorySize, ASMEM);

    prep_w_kernel<<<(3 * Dc * Hc / 4) / 256, 256>>>(Wq, Wk, Wv);

    proj_kernel<<<(Bc * Tc) / 128, 384, PSMEM>>>(x, bq, bk, bv);

    dim3 ag(SLOTS, Bc);
    attn_partial_kernel<<<ag, 128, ASMEM>>>(out);

    merge_kernel<<<(Bc * Tc) / 8, 256>>>(out);
}

// round 16
// speedup vs baseline: 1.2754x; 1.0195x over previous
#include <cuda_runtime.h>
#include <cuda_bf16.h>
#include <cstdint>

constexpr int Bc = 8;
constexpr int Tc = 2048;
constexpr int Dc = 1024;
constexpr int Hc = 64;

// q/k/v projections (stored tf32-rounded f32)
__device__ float g_q[Bc * Tc * Hc];
__device__ float g_k[Bc * Tc * Hc];
__device__ float g_v[Bc * Tc * Hc];

// tf32-rounded copies of the weights
__device__ float g_wq[Dc * Hc];
__device__ float g_wk[Dc * Hc];
__device__ float g_wv[Dc * Hc];

// split-KV partials: chunk = 4 KV tiles. qtile i (of 32) has ceil((i+1)/4)
// chunks; per batch = 144 slots. group gg: qtiles 4gg..4gg+3, gg+1 chunks each.
constexpr int SLOTS = 144;
__device__ float g_po[Bc * SLOTS * 64 * 64];   // unnormalized O
__device__ float g_pm[Bc * SLOTS * 64];        // row max (exp2 space)
__device__ float g_pl[Bc * SLOTS * 64];        // row sum

__device__ __forceinline__ uint32_t f2tf32(float x) {
    uint32_t u;
    asm("cvt.rna.tf32.f32 %0, %1;" : "=r"(u) : "f"(x));
    return u;
}
__device__ __forceinline__ float ex2f(float x) {
    float y;
    asm("ex2.approx.ftz.f32 %0, %1;" : "=f"(y) : "f"(x));
    return y;
}
__device__ __forceinline__ void mma_tf32(float* c,
    uint32_t a0, uint32_t a1, uint32_t a2, uint32_t a3,
    uint32_t b0, uint32_t b1)
{
    asm volatile(
        "mma.sync.aligned.m16n8k8.row.col.f32.tf32.tf32.f32 "
        "{%0,%1,%2,%3}, {%4,%5,%6,%7}, {%8,%9}, {%0,%1,%2,%3};"
        : "+f"(c[0]), "+f"(c[1]), "+f"(c[2]), "+f"(c[3])
        : "r"(a0), "r"(a1), "r"(a2), "r"(a3), "r"(b0), "r"(b1));
}
__device__ __forceinline__ uint32_t smem_u32(const void* p) {
    return (uint32_t)__cvta_generic_to_shared(p);
}
__device__ __forceinline__ void cpa16(uint32_t dst, const void* src) {
    asm volatile("cp.async.ca.shared.global [%0], [%1], 16;" :: "r"(dst), "l"(src));
}
#define CP_COMMIT() asm volatile("cp.async.commit_group;")

// ---------------------------------------------------------------------------
// W prepass: tf32-round the three weight matrices into scratch.
// ---------------------------------------------------------------------------
__global__ __launch_bounds__(256) void prep_w_kernel(
    const float* __restrict__ Wq, const float* __restrict__ Wk, const float* __restrict__ Wv)
{
    const int idx = blockIdx.x * 256 + threadIdx.x;
    const int p   = idx / (Dc * Hc / 4);
    const int r   = idx % (Dc * Hc / 4);
    const float* src = (p == 0) ? Wq : (p == 1) ? Wk : Wv;
    float* dst = (p == 0) ? g_wq : (p == 1) ? g_wk : g_wv;
    float4 v = *(const float4*)(src + r * 4);
    float4 o = make_float4(__uint_as_float(f2tf32(v.x)), __uint_as_float(f2tf32(v.y)),
                           __uint_as_float(f2tf32(v.z)), __uint_as_float(f2tf32(v.w)));
    *(float4*)(dst + r * 4) = o;
}

// ---------------------------------------------------------------------------
// Fused projection (unchanged: BM=128, 3-stage cp.async, raw B frags,
// cvt-at-A-fragment-load, tf32-rounded epilogue). ~48us, 92% of mma.sync floor.
// ---------------------------------------------------------------------------
#define XPAD   36
#define WPAD   72
#define XS_F   (128 * XPAD)
#define STAGEF (XS_F + 3 * 32 * WPAD)
#define PSTAGES 3
#define PSMEM  (PSTAGES * STAGEF * 4)

__device__ __forceinline__ void proj_stage_async(
    uint32_t sb, const float* __restrict__ x,
    const float* const* Wp, int m0, int k0, int t)
{
    for (int idx = t; idx < 1024; idx += 384) {
        int row = idx >> 3;
        int c4  = (idx & 7) << 2;
        cpa16(sb + (uint32_t)(row * XPAD + c4) * 4,
              x + (size_t)(m0 + row) * Dc + k0 + c4);
    }
#pragma unroll
    for (int i = 0; i < 4; i++) {
        int idx = t + i * 384;
        int p   = idx >> 9;
        int rem = idx & 511;
        int row = rem >> 4;
        int c4  = (rem & 15) << 2;
        cpa16(sb + (uint32_t)(XS_F + (p * 32 + row) * WPAD + c4) * 4,
              Wp[p] + (size_t)(k0 + row) * Hc + c4);
    }
}

__global__ __launch_bounds__(384, 1) void proj_kernel(
    const float* __restrict__ x,
    const float* __restrict__ bq, const float* __restrict__ bk, const float* __restrict__ bv)
{
    extern __shared__ float psm[];
    const float* Wp[3] = { g_wq, g_wk, g_wv };

    const int t    = threadIdx.x;
    const int w    = t >> 5;
    const int p    = w >> 2;
    const int ww   = w & 3;
    const int lane = t & 31;
    const int g    = lane >> 2;
    const int q4   = lane & 3;
    const int m0   = blockIdx.x * 128;

    const uint32_t sb = smem_u32(psm);

    float acc[2][8][4];
#pragma unroll
    for (int i = 0; i < 2; i++)
#pragma unroll
        for (int nf = 0; nf < 8; nf++)
#pragma unroll
            for (int j = 0; j < 4; j++) acc[i][nf][j] = 0.f;

    proj_stage_async(sb,              x, Wp, m0, 0,  t);
    CP_COMMIT();
    proj_stage_async(sb + STAGEF * 4, x, Wp, m0, 32, t);
    CP_COMMIT();

    for (int it = 0; it < 32; it++) {
        if (it < 30) {
            proj_stage_async(sb + (uint32_t)((it + 2) % 3) * STAGEF * 4,
                             x, Wp, m0, (it + 2) * 32, t);
            CP_COMMIT();
            asm volatile("cp.async.wait_group 2;");
        } else if (it == 30) {
            asm volatile("cp.async.wait_group 1;");
        } else {
            asm volatile("cp.async.wait_group 0;");
        }
        __syncthreads();

        const float* Xs = psm + (it % 3) * STAGEF;
        const float* Ws = Xs + XS_F + p * 32 * WPAD;

#pragma unroll
        for (int ks = 0; ks < 4; ks++) {
            const int kc = ks * 8 + q4;
            uint32_t a[2][4];
#pragma unroll
            for (int i = 0; i < 2; i++) {
                const int r = ww * 32 + i * 16 + g;
                a[i][0] = f2tf32(Xs[(r    ) * XPAD + kc]);
                a[i][1] = f2tf32(Xs[(r + 8) * XPAD + kc]);
                a[i][2] = f2tf32(Xs[(r    ) * XPAD + kc + 4]);
                a[i][3] = f2tf32(Xs[(r + 8) * XPAD + kc + 4]);
            }
#pragma unroll
            for (int nf = 0; nf < 8; nf++) {
                uint32_t b0 = __float_as_uint(Ws[(kc    ) * WPAD + nf * 8 + g]);
                uint32_t b1 = __float_as_uint(Ws[(kc + 4) * WPAD + nf * 8 + g]);
                mma_tf32(acc[0][nf], a[0][0], a[0][1], a[0][2], a[0][3], b0, b1);
                mma_tf32(acc[1][nf], a[1][0], a[1][1], a[1][2], a[1][3], b0, b1);
            }
        }
        __syncthreads();
    }

    const float* biases[3] = { bq, bk, bv };
    float* outs[3] = { g_q, g_k, g_v };
    float* out = outs[p];
    const float* bias = biases[p];
#pragma unroll
    for (int i = 0; i < 2; i++) {
        const int r0 = m0 + ww * 32 + i * 16 + g;
#pragma unroll
        for (int nf = 0; nf < 8; nf++) {
            int col = nf * 8 + 2 * q4;
            float b0 = bias[col], b1 = bias[col + 1];
            float2 v0 = make_float2(__uint_as_float(f2tf32(acc[i][nf][0] + b0)),
                                    __uint_as_float(f2tf32(acc[i][nf][1] + b1)));
            float2 v1 = make_float2(__uint_as_float(f2tf32(acc[i][nf][2] + b0)),
                                    __uint_as_float(f2tf32(acc[i][nf][3] + b1)));
            *(float2*)(out + (size_t)r0 * Hc + col)       = v0;
            *(float2*)(out + (size_t)(r0 + 8) * Hc + col) = v1;
        }
    }
}

// ---------------------------------------------------------------------------
// Attention partials (unchanged from round 15: chunk = 4 KV tiles,
// 64-query blocks, 4 warps, cp.async 2-stage, raw K/V frags, shuffle PV).
// ---------------------------------------------------------------------------
#define KPAD 68
#define VPAD 72
#define KTILE (64 * KPAD)
#define VTILE (64 * VPAD)
#define STF   (KTILE + VTILE)
#define ASMEM (2 * STF * 4)

__device__ __forceinline__ void attn_stage_async(
    uint32_t sb, const float* __restrict__ kb, const float* __restrict__ vb,
    int kn0, int t)
{
#pragma unroll
    for (int i = 0; i < 8; i++) {
        int idx = t + i * 128;
        int row = idx >> 4;
        int c4  = (idx & 15) << 2;
        cpa16(sb + (uint32_t)(row * KPAD + c4) * 4,
              kb + (size_t)(kn0 + row) * Hc + c4);
    }
#pragma unroll
    for (int i = 0; i < 8; i++) {
        int idx = t + i * 128;
        int row = idx >> 4;
        int c4  = (idx & 15) << 2;
        cpa16(sb + (uint32_t)(KTILE + row * VPAD + c4) * 4,
              vb + (size_t)(kn0 + row) * Hc + c4);
    }
}

__global__ __launch_bounds__(128) void attn_partial_kernel(float* __restrict__ gout)
{
    extern __shared__ float sm[];
    const uint32_t sb = smem_u32(sm);

    const int b   = blockIdx.y;
    const int idx = (int)(gridDim.x - 1 - blockIdx.x);   // heavy chunks first

    int qt = 0, ch = 0;
#pragma unroll
    for (int gg = 7; gg >= 0; gg--) {
        int s = 2 * gg * (gg + 1);
        if (idx >= s) { qt = 4 * gg + (idx - s) / (gg + 1); ch = (idx - s) % (gg + 1); break; }
    }
    const int q0  = qt * 64;
    const int kt0 = ch * 4;
    const int kt1 = min(kt0 + 4, qt + 1);

    const int t    = threadIdx.x;
    const int w    = t >> 5;
    const int lane = t & 31;
    const int g    = lane >> 2;
    const int q4   = lane & 3;

    const float* qb = g_q + (size_t)b * Tc * Hc;
    const float* kb = g_k + (size_t)b * Tc * Hc;
    const float* vb = g_v + (size_t)b * Tc * Hc;

    attn_stage_async(sb, kb, vb, kt0 * 64, t);
    CP_COMMIT();

    const float SC = 0.125f * 1.44269504f;
    uint32_t qa[8][4];
    {
        const float* r0 = qb + (size_t)(q0 + w * 16 + g) * Hc;
        const float* r1 = r0 + 8 * Hc;
#pragma unroll
        for (int ks = 0; ks < 8; ks++) {
            qa[ks][0] = f2tf32(r0[ks * 8 + q4] * SC);
            qa[ks][1] = f2tf32(r1[ks * 8 + q4] * SC);
            qa[ks][2] = f2tf32(r0[ks * 8 + q4 + 4] * SC);
            qa[ks][3] = f2tf32(r1[ks * 8 + q4 + 4] * SC);
        }
    }

    float o[8][4];
#pragma unroll
    for (int nf = 0; nf < 8; nf++)
#pragma unroll
        for (int j = 0; j < 4; j++) o[nf][j] = 0.f;
    float m0 = -1e30f, m1 = -1e30f, l0 = 0.f, l1 = 0.f;

    const int srcA = 4 * g + (q4 >> 1);
    const int srcB = srcA + 2;
    const bool odd = (q4 & 1);

    for (int kt = kt0; kt < kt1; kt++) {
        const int buf = (kt - kt0) & 1;
        if (kt + 1 < kt1) {
            attn_stage_async(sb + (uint32_t)(buf ^ 1) * STF * 4, kb, vb, (kt + 1) * 64, t);
            CP_COMMIT();
            asm volatile("cp.async.wait_group 1;");
        } else {
            asm volatile("cp.async.wait_group 0;");
        }
        __syncthreads();

        const float* Ks = sm + buf * STF;
        const float* Vs = Ks + KTILE;
        const int kn0 = kt * 64;

        float sf[8][4];
#pragma unroll
        for (int nf = 0; nf < 8; nf++) {
            sf[nf][0] = sf[nf][1] = sf[nf][2] = sf[nf][3] = 0.f;
#pragma unroll
            for (int ks = 0; ks < 8; ks++) {
                uint32_t b0 = __float_as_uint(Ks[(nf * 8 + g) * KPAD + ks * 8 + q4]);
                uint32_t b1 = __float_as_uint(Ks[(nf * 8 + g) * KPAD + ks * 8 + q4 + 4]);
                mma_tf32(sf[nf], qa[ks][0], qa[ks][1], qa[ks][2], qa[ks][3], b0, b1);
            }
        }

        if (kt == qt) {
            const int r0 = q0 + w * 16 + g;
            const int r1 = r0 + 8;
#pragma unroll
            for (int nf = 0; nf < 8; nf++) {
                int c0 = kn0 + nf * 8 + 2 * q4;
                if (c0     > r0) sf[nf][0] = -1e30f;
                if (c0 + 1 > r0) sf[nf][1] = -1e30f;
                if (c0     > r1) sf[nf][2] = -1e30f;
                if (c0 + 1 > r1) sf[nf][3] = -1e30f;
            }
        }

        float mx0 = -1e30f, mx1 = -1e30f;
#pragma unroll
        for (int nf = 0; nf < 8; nf++) {
            mx0 = fmaxf(mx0, fmaxf(sf[nf][0], sf[nf][1]));
            mx1 = fmaxf(mx1, fmaxf(sf[nf][2], sf[nf][3]));
        }
        mx0 = fmaxf(mx0, __shfl_xor_sync(0xffffffffu, mx0, 1));
        mx0 = fmaxf(mx0, __shfl_xor_sync(0xffffffffu, mx0, 2));
        mx1 = fmaxf(mx1, __shfl_xor_sync(0xffffffffu, mx1, 1));
        mx1 = fmaxf(mx1, __shfl_xor_sync(0xffffffffu, mx1, 2));

        float mn0 = fmaxf(m0, mx0), mn1 = fmaxf(m1, mx1);
        float sc0 = ex2f(m0 - mn0), sc1 = ex2f(m1 - mn1);

        float rs0 = 0.f, rs1 = 0.f;
#pragma unroll
        for (int nf = 0; nf < 8; nf++) {
            sf[nf][0] = ex2f(sf[nf][0] - mn0);
            sf[nf][1] = ex2f(sf[nf][1] - mn0);
            sf[nf][2] = ex2f(sf[nf][2] - mn1);
            sf[nf][3] = ex2f(sf[nf][3] - mn1);
            rs0 += sf[nf][0] + sf[nf][1];
            rs1 += sf[nf][2] + sf[nf][3];
        }
        rs0 += __shfl_xor_sync(0xffffffffu, rs0, 1);
        rs0 += __shfl_xor_sync(0xffffffffu, rs0, 2);
        rs1 += __shfl_xor_sync(0xffffffffu, rs1, 1);
        rs1 += __shfl_xor_sync(0xffffffffu, rs1, 2);

        l0 = l0 * sc0 + rs0;  m0 = mn0;
        l1 = l1 * sc1 + rs1;  m1 = mn1;
#pragma unroll
        for (int nf = 0; nf < 8; nf++) {
            o[nf][0] *= sc0;  o[nf][1] *= sc0;
            o[nf][2] *= sc1;  o[nf][3] *= sc1;
        }

#pragma unroll
        for (int ks = 0; ks < 8; ks++) {
            float s0A = __shfl_sync(0xffffffffu, sf[ks][0], srcA);
            float s1A = __shfl_sync(0xffffffffu, sf[ks][1], srcA);
            float s2A = __shfl_sync(0xffffffffu, sf[ks][2], srcA);
            float s3A = __shfl_sync(0xffffffffu, sf[ks][3], srcA);
            float s0B = __shfl_sync(0xffffffffu, sf[ks][0], srcB);
            float s1B = __shfl_sync(0xffffffffu, sf[ks][1], srcB);
            float s2B = __shfl_sync(0xffffffffu, sf[ks][2], srcB);
            float s3B = __shfl_sync(0xffffffffu, sf[ks][3], srcB);
            uint32_t a0 = f2tf32(odd ? s1A : s0A);
            uint32_t a1 = f2tf32(odd ? s3A : s2A);
            uint32_t a2 = f2tf32(odd ? s1B : s0B);
            uint32_t a3 = f2tf32(odd ? s3B : s2B);
#pragma unroll
            for (int nf = 0; nf < 8; nf++) {
                uint32_t b0 = __float_as_uint(Vs[(ks * 8 + q4    ) * VPAD + nf * 8 + g]);
                uint32_t b1 = __float_as_uint(Vs[(ks * 8 + q4 + 4) * VPAD + nf * 8 + g]);
                mma_tf32(o[nf], a0, a1, a2, a3, b0, b1);
            }
        }
        __syncthreads();
    }

    const int r0 = w * 16 + g;
    const int r1 = r0 + 8;

    if (qt < 4) {
        float inv0 = 1.f / l0, inv1 = 1.f / l1;
        float* po = gout + ((size_t)b * Tc + q0) * Hc;
#pragma unroll
        for (int nf = 0; nf < 8; nf++) {
            int col = nf * 8 + 2 * q4;
            *(float2*)(po + (size_t)r0 * Hc + col) = make_float2(o[nf][0] * inv0, o[nf][1] * inv0);
            *(float2*)(po + (size_t)r1 * Hc + col) = make_float2(o[nf][2] * inv1, o[nf][3] * inv1);
        }
    } else {
        const int slot = b * SLOTS + idx;
        float* po = g_po + (size_t)slot * 4096;
#pragma unroll
        for (int nf = 0; nf < 8; nf++) {
            int col = nf * 8 + 2 * q4;
            *(float2*)(po + r0 * 64 + col) = make_float2(o[nf][0], o[nf][1]);
            *(float2*)(po + r1 * 64 + col) = make_float2(o[nf][2], o[nf][3]);
        }
        if (q4 == 0) {
            g_pm[slot * 64 + r0] = m0;  g_pm[slot * 64 + r1] = m1;
            g_pl[slot * 64 + r0] = l0;  g_pl[slot * 64 + r1] = l1;
        }
    }
}

// ---------------------------------------------------------------------------
// Merge v2: all partial loads hoisted into registers (MLP ~17) before any
// arithmetic. <=8 partials per row; qt<4 rows written directly by attn.
// ---------------------------------------------------------------------------
__global__ __launch_bounds__(256) void merge_kernel(float* __restrict__ out)
{
    const int gid  = blockIdx.x * 8 + (threadIdx.x >> 5);
    const int lane = threadIdx.x & 31;
    const int b = gid >> 11;
    const int q = gid & 2047;
    const int qt    = q >> 6;
    if (qt < 4) return;                 // written directly by attn_partial
    const int rowin = q & 63;
    const int gg    = qt >> 2;
    const int nch   = gg + 1;           // 2..8
    const int base  = b * SLOTS + 2 * gg * (gg + 1) + (qt - 4 * gg) * (gg + 1);
    const int col   = lane * 2;

    // issue ALL loads first (predicated, fully unrolled) -> deep MLP
    float  mv[8], pl[8];
    float2 ov[8];
#pragma unroll
    for (int c = 0; c < 8; c++) {
        if (c < nch) {
            mv[c] = g_pm[(base + c) * 64 + rowin];
            pl[c] = g_pl[(base + c) * 64 + rowin];
            ov[c] = *(const float2*)(g_po + ((size_t)(base + c) * 64 + rowin) * 64 + col);
        } else {
            mv[c] = -1e30f;
            pl[c] = 0.f;
            ov[c] = make_float2(0.f, 0.f);
        }
    }

    float M = mv[0];
#pragma unroll
    for (int c = 1; c < 8; c++) M = fmaxf(M, mv[c]);

    float L = 0.f, o0 = 0.f, o1 = 0.f;
#pragma unroll
    for (int c = 0; c < 8; c++) {
        float wgt = ex2f(mv[c] - M);     // zero contribution for c >= nch
        L  += wgt * pl[c];
        o0 += wgt * ov[c].x;
        o1 += wgt * ov[c].y;
    }
    float inv = 1.f / L;
    *(float2*)(out + ((size_t)b * Tc + q) * Hc + col) = make_float2(o0 * inv, o1 * inv);
}

// ---------------------------------------------------------------------------
extern "C" void kernel_launch(void* const* d_in, const int* in_sizes, int n_in,
                              void* d_out, int out_size)
{
    (void)in_sizes; (void)n_in; (void)out_size;
    const float* x  = (const float*)d_in[0];
    const float* Wk = (const float*)d_in[1];
    const float* bk = (const float*)d_in[2];
    const float* Wq = (const float*)d_in[3];
    const float* bq = (const float*)d_in[4];
    const float* Wv = (const float*)d_in[5];
    const float* bv = (const float*)d_in[6];
    float* out = (float*)d_out;

    cudaFuncSetAttribute(proj_kernel, cudaFuncAttributeMaxDynamicSharedMemorySize, PSMEM);
    cudaFuncSetAttribute(attn_partial_kernel, cudaFuncAttributeMaxDynamicSharedMemorySize, ASMEM);

    prep_w_kernel<<<(3 * Dc * Hc / 4) / 256, 256>>>(Wq, Wk, Wv);

    proj_kernel<<<(Bc * Tc) / 128, 384, PSMEM>>>(x, bq, bk, bv);

    dim3 ag(SLOTS, Bc);
    attn_partial_kernel<<<ag, 128, ASMEM>>>(out);

    merge_kernel<<<(Bc * Tc) / 8, 256>>>(out);
}

// round 17
// speedup vs baseline: 1.7469x; 1.3697x over previous
#include <cuda_runtime.h>
#include <cuda_bf16.h>
#include <cuda_fp16.h>
#include <cstdint>

constexpr int Bc = 8;
constexpr int Tc = 2048;
constexpr int Dc = 1024;
constexpr int Hc = 64;

// q/k projections (fp16, natural [b][t][h]); V stored TRANSPOSED [b][h][t]
__device__ __half g_q[Bc * Tc * Hc];
__device__ __half g_k[Bc * Tc * Hc];
__device__ __half g_vT[Bc * Hc * Tc];

// fp16 transposed weights: [p][n][k]
__device__ __half g_wT[3 * Hc * Dc];

// split-KV partials (f32): chunk = 4 KV tiles; 144 slots/batch
constexpr int SLOTS = 144;
__device__ float g_po[Bc * SLOTS * 64 * 64];
__device__ float g_pm[Bc * SLOTS * 64];
__device__ float g_pl[Bc * SLOTS * 64];

__device__ __forceinline__ float ex2f(float x) {
    float y;
    asm("ex2.approx.ftz.f32 %0, %1;" : "=f"(y) : "f"(x));
    return y;
}
__device__ __forceinline__ void mma16(float* c,
    uint32_t a0, uint32_t a1, uint32_t a2, uint32_t a3,
    uint32_t b0, uint32_t b1)
{
    asm volatile(
        "mma.sync.aligned.m16n8k16.row.col.f32.f16.f16.f32 "
        "{%0,%1,%2,%3}, {%4,%5,%6,%7}, {%8,%9}, {%0,%1,%2,%3};"
        : "+f"(c[0]), "+f"(c[1]), "+f"(c[2]), "+f"(c[3])
        : "r"(a0), "r"(a1), "r"(a2), "r"(a3), "r"(b0), "r"(b1));
}
__device__ __forceinline__ uint32_t packh2(float x, float y) {
    __half2 h = __floats2half2_rn(x, y);
    return *(uint32_t*)&h;
}
__device__ __forceinline__ uint32_t smem_u32(const void* p) {
    return (uint32_t)__cvta_generic_to_shared(p);
}
__device__ __forceinline__ void cpa16(uint32_t dst, const void* src) {
    asm volatile("cp.async.ca.shared.global [%0], [%1], 16;" :: "r"(dst), "l"(src));
}
#define CP_COMMIT() asm volatile("cp.async.commit_group;")

// ---------------------------------------------------------------------------
// W prepass: fp16 transpose W[k][n] -> g_wT[p][n][k].
// ---------------------------------------------------------------------------
__global__ __launch_bounds__(256) void prep_w_kernel(
    const float* __restrict__ Wq, const float* __restrict__ Wk, const float* __restrict__ Wv)
{
    const int idx = blockIdx.x * 256 + threadIdx.x;   // over 3*64*1024
    const int p   = idx >> 16;
    const int rem = idx & 65535;
    const int n   = rem >> 10;
    const int k   = rem & 1023;
    const float* src = (p == 0) ? Wq : (p == 1) ? Wk : Wv;
    g_wT[idx] = __float2half_rn(src[(size_t)k * Hc + n]);
}

// ---------------------------------------------------------------------------
// Fused projection, fp16 MMA (m16n8k16). BM=128, 3-stage cp.async.
// x staged f32 (cvt at A-fragment pack); W staged raw fp16 from g_wT.
// Epilogue writes fp16 q/k and TRANSPOSED fp16 V.
// ---------------------------------------------------------------------------
#define XPAD    36
#define WPADH   40                       // halves per W^T row (32 data + pad)
#define XBYTES  (128 * XPAD * 4)         // 18432
#define WBYTES  (3 * 64 * WPADH * 2)     // 15360
#define STAGEB  (XBYTES + WBYTES)        // 33792
#define PSMEM   (3 * STAGEB)             // 101376

__device__ __forceinline__ void proj_stage_async(
    uint32_t sb, const float* __restrict__ x, int m0, int k0, int t)
{
    // x tile [128][32] f32: 1024 chunks
    for (int idx = t; idx < 1024; idx += 384) {
        int row = idx >> 3;
        int c4  = (idx & 7) << 2;
        cpa16(sb + (uint32_t)(row * XPAD + c4) * 4,
              x + (size_t)(m0 + row) * Dc + k0 + c4);
    }
    // W^T tiles 3x[64 rows][32 halves]: 768 chunks (8 halves each)
#pragma unroll
    for (int i = 0; i < 2; i++) {
        int idx = t + i * 384;
        if (idx < 768) {
            int p   = idx >> 8;
            int rem = idx & 255;
            int row = rem >> 2;
            int c8  = (rem & 3) << 3;
            cpa16(sb + XBYTES + (uint32_t)(p * 64 * WPADH + row * WPADH + c8) * 2,
                  g_wT + (size_t)p * 65536 + (size_t)row * Dc + k0 + c8);
        }
    }
}

__global__ __launch_bounds__(384, 1) void proj_kernel(
    const float* __restrict__ x,
    const float* __restrict__ bq, const float* __restrict__ bk, const float* __restrict__ bv)
{
    extern __shared__ char psm[];

    const int t    = threadIdx.x;
    const int w    = t >> 5;
    const int p    = w >> 2;
    const int ww   = w & 3;
    const int lane = t & 31;
    const int g    = lane >> 2;
    const int q4   = lane & 3;
    const int m0   = blockIdx.x * 128;

    const uint32_t sb = smem_u32(psm);

    float acc[2][8][4];
#pragma unroll
    for (int i = 0; i < 2; i++)
#pragma unroll
        for (int nf = 0; nf < 8; nf++)
#pragma unroll
            for (int j = 0; j < 4; j++) acc[i][nf][j] = 0.f;

    proj_stage_async(sb,          x, m0, 0,  t);
    CP_COMMIT();
    proj_stage_async(sb + STAGEB, x, m0, 32, t);
    CP_COMMIT();

    for (int it = 0; it < 32; it++) {
        if (it < 30) {
            proj_stage_async(sb + (uint32_t)((it + 2) % 3) * STAGEB,
                             x, m0, (it + 2) * 32, t);
            CP_COMMIT();
            asm volatile("cp.async.wait_group 2;");
        } else if (it == 30) {
            asm volatile("cp.async.wait_group 1;");
        } else {
            asm volatile("cp.async.wait_group 0;");
        }
        __syncthreads();

        const float*  Xs  = (const float*)(psm + (it % 3) * STAGEB);
        const __half* WsT = (const __half*)(psm + (it % 3) * STAGEB + XBYTES) + p * 64 * WPADH;

#pragma unroll
        for (int ks = 0; ks < 2; ks++) {            // two k16 steps
            const int klo = ks * 16 + 2 * q4;
            uint32_t a[2][4];
#pragma unroll
            for (int i = 0; i < 2; i++) {
                const int r = ww * 32 + i * 16 + g;
                float2 x0 = *(const float2*)&Xs[(r    ) * XPAD + klo];
                float2 x1 = *(const float2*)&Xs[(r + 8) * XPAD + klo];
                float2 x2 = *(const float2*)&Xs[(r    ) * XPAD + klo + 8];
                float2 x3 = *(const float2*)&Xs[(r + 8) * XPAD + klo + 8];
                a[i][0] = packh2(x0.x, x0.y);
                a[i][1] = packh2(x1.x, x1.y);
                a[i][2] = packh2(x2.x, x2.y);
                a[i][3] = packh2(x3.x, x3.y);
            }
#pragma unroll
            for (int nf = 0; nf < 8; nf++) {
                const __half* wr = WsT + (nf * 8 + g) * WPADH + klo;
                uint32_t b0 = *(const uint32_t*)wr;
                uint32_t b1 = *(const uint32_t*)(wr + 8);
                mma16(acc[0][nf], a[0][0], a[0][1], a[0][2], a[0][3], b0, b1);
                mma16(acc[1][nf], a[1][0], a[1][1], a[1][2], a[1][3], b0, b1);
            }
        }
        __syncthreads();
    }

    const float* biases[3] = { bq, bk, bv };
#pragma unroll
    for (int i = 0; i < 2; i++) {
        const int m = m0 + ww * 32 + i * 16 + g;        // rows m, m+8
#pragma unroll
        for (int nf = 0; nf < 8; nf++) {
            int col = nf * 8 + 2 * q4;
            float b0 = biases[p][col], b1 = biases[p][col + 1];
            float v00 = acc[i][nf][0] + b0, v01 = acc[i][nf][1] + b1;
            float v10 = acc[i][nf][2] + b0, v11 = acc[i][nf][3] + b1;
            if (p < 2) {
                __half* out = (p == 0) ? g_q : g_k;
                *(uint32_t*)&out[(size_t)m * Hc + col]       = packh2(v00, v01);
                *(uint32_t*)&out[(size_t)(m + 8) * Hc + col] = packh2(v10, v11);
            } else {
                // V transposed: g_vT[(b*64 + col)*2048 + t]
                const int bb = m >> 11, tt = m & 2047;
                g_vT[((size_t)bb * Hc + col    ) * Tc + tt]     = __float2half_rn(v00);
                g_vT[((size_t)bb * Hc + col + 1) * Tc + tt]     = __float2half_rn(v01);
                g_vT[((size_t)bb * Hc + col    ) * Tc + tt + 8] = __float2half_rn(v10);
                g_vT[((size_t)bb * Hc + col + 1) * Tc + tt + 8] = __float2half_rn(v11);
            }
        }
    }
}

// ---------------------------------------------------------------------------
// Attention partials, fp16 MMA. chunk = 4 KV tiles; 64-query blocks, 4 warps.
// K staged raw fp16 [kv][72h]; V^T staged raw fp16 [h][72h]. PV A-frags come
// straight from S accumulators (fp16 layout identity) - no shuffles, no smem P.
// ---------------------------------------------------------------------------
#define KVPADH 72
#define TILEH  (64 * KVPADH)           // halves per tile
#define STFB   (2 * TILEH * 2)         // bytes per stage (K + V^T) = 18432
#define ASMEM  (2 * STFB)              // 36864

__device__ __forceinline__ void attn_stage_async(
    uint32_t sb, const __half* __restrict__ kb, const __half* __restrict__ vtb,
    int kn0, int t)
{
    // K: 64 rows x 64 halves = 512 chunks
#pragma unroll
    for (int i = 0; i < 4; i++) {
        int idx = t + i * 128;
        int row = idx >> 3;
        int c8  = (idx & 7) << 3;
        cpa16(sb + (uint32_t)(row * KVPADH + c8) * 2,
              kb + (size_t)(kn0 + row) * Hc + c8);
    }
    // V^T: 64 h-rows x 64 halves (t-range kn0..kn0+63) = 512 chunks
#pragma unroll
    for (int i = 0; i < 4; i++) {
        int idx = t + i * 128;
        int row = idx >> 3;
        int c8  = (idx & 7) << 3;
        cpa16(sb + (uint32_t)(TILEH + row * KVPADH + c8) * 2,
              vtb + (size_t)row * Tc + kn0 + c8);
    }
}

__global__ __launch_bounds__(128) void attn_partial_kernel(float* __restrict__ gout)
{
    extern __shared__ __half smh[];
    const uint32_t sb = smem_u32(smh);

    const int b   = blockIdx.y;
    const int idx = (int)(gridDim.x - 1 - blockIdx.x);   // heavy chunks first

    int qt = 0, ch = 0;
#pragma unroll
    for (int gg = 7; gg >= 0; gg--) {
        int s = 2 * gg * (gg + 1);
        if (idx >= s) { qt = 4 * gg + (idx - s) / (gg + 1); ch = (idx - s) % (gg + 1); break; }
    }
    const int q0  = qt * 64;
    const int kt0 = ch * 4;
    const int kt1 = min(kt0 + 4, qt + 1);

    const int t    = threadIdx.x;
    const int w    = t >> 5;
    const int lane = t & 31;
    const int g    = lane >> 2;
    const int q4   = lane & 3;

    const __half* qb  = g_q  + (size_t)b * Tc * Hc;
    const __half* kb  = g_k  + (size_t)b * Tc * Hc;
    const __half* vtb = g_vT + (size_t)b * Hc * Tc;

    attn_stage_async(sb, kb, vtb, kt0 * 64, t);
    CP_COMMIT();

    // Q fragments, scaled by (1/sqrt(H))*log2(e) in half2
    const __half2 SC2 = __float2half2_rn(0.125f * 1.44269504f);
    uint32_t qa[4][4];
    {
        const __half* r0 = qb + (size_t)(q0 + w * 16 + g) * Hc;
        const __half* r1 = r0 + 8 * Hc;
#pragma unroll
        for (int ks = 0; ks < 4; ks++) {
            const int klo = ks * 16 + 2 * q4;
            __half2 h0 = __hmul2(*(const __half2*)&r0[klo],     SC2);
            __half2 h1 = __hmul2(*(const __half2*)&r1[klo],     SC2);
            __half2 h2 = __hmul2(*(const __half2*)&r0[klo + 8], SC2);
            __half2 h3 = __hmul2(*(const __half2*)&r1[klo + 8], SC2);
            qa[ks][0] = *(uint32_t*)&h0;
            qa[ks][1] = *(uint32_t*)&h1;
            qa[ks][2] = *(uint32_t*)&h2;
            qa[ks][3] = *(uint32_t*)&h3;
        }
    }

    float o[8][4];
#pragma unroll
    for (int nf = 0; nf < 8; nf++)
#pragma unroll
        for (int j = 0; j < 4; j++) o[nf][j] = 0.f;
    float m0 = -1e30f, m1 = -1e30f, l0 = 0.f, l1 = 0.f;

    for (int kt = kt0; kt < kt1; kt++) {
        const int buf = (kt - kt0) & 1;
        if (kt + 1 < kt1) {
            attn_stage_async(sb + (uint32_t)(buf ^ 1) * STFB, kb, vtb, (kt + 1) * 64, t);
            CP_COMMIT();
            asm volatile("cp.async.wait_group 1;");
        } else {
            asm volatile("cp.async.wait_group 0;");
        }
        __syncthreads();

        const __half* Ks  = smh + buf * (2 * TILEH);
        const __half* VsT = Ks + TILEH;
        const int kn0 = kt * 64;

        // S = Q @ K^T (fp16, 4 k16 steps)
        float sf[8][4];
#pragma unroll
        for (int nf = 0; nf < 8; nf++)
            sf[nf][0] = sf[nf][1] = sf[nf][2] = sf[nf][3] = 0.f;
#pragma unroll
        for (int ks = 0; ks < 4; ks++) {
            const int klo = ks * 16 + 2 * q4;
#pragma unroll
            for (int nf = 0; nf < 8; nf++) {
                const __half* kr = Ks + (nf * 8 + g) * KVPADH + klo;
                uint32_t b0 = *(const uint32_t*)kr;
                uint32_t b1 = *(const uint32_t*)(kr + 8);
                mma16(sf[nf], qa[ks][0], qa[ks][1], qa[ks][2], qa[ks][3], b0, b1);
            }
        }

        if (kt == qt) {   // diagonal tile: causal mask
            const int r0 = q0 + w * 16 + g;
            const int r1 = r0 + 8;
#pragma unroll
            for (int nf = 0; nf < 8; nf++) {
                int c0 = kn0 + nf * 8 + 2 * q4;
                if (c0     > r0) sf[nf][0] = -1e30f;
                if (c0 + 1 > r0) sf[nf][1] = -1e30f;
                if (c0     > r1) sf[nf][2] = -1e30f;
                if (c0 + 1 > r1) sf[nf][3] = -1e30f;
            }
        }

        // online softmax (exp2 space)
        float mx0 = -1e30f, mx1 = -1e30f;
#pragma unroll
        for (int nf = 0; nf < 8; nf++) {
            mx0 = fmaxf(mx0, fmaxf(sf[nf][0], sf[nf][1]));
            mx1 = fmaxf(mx1, fmaxf(sf[nf][2], sf[nf][3]));
        }
        mx0 = fmaxf(mx0, __shfl_xor_sync(0xffffffffu, mx0, 1));
        mx0 = fmaxf(mx0, __shfl_xor_sync(0xffffffffu, mx0, 2));
        mx1 = fmaxf(mx1, __shfl_xor_sync(0xffffffffu, mx1, 1));
        mx1 = fmaxf(mx1, __shfl_xor_sync(0xffffffffu, mx1, 2));

        float mn0 = fmaxf(m0, mx0), mn1 = fmaxf(m1, mx1);
        float sc0 = ex2f(m0 - mn0), sc1 = ex2f(m1 - mn1);

        float rs0 = 0.f, rs1 = 0.f;
#pragma unroll
        for (int nf = 0; nf < 8; nf++) {
            sf[nf][0] = ex2f(sf[nf][0] - mn0);
            sf[nf][1] = ex2f(sf[nf][1] - mn0);
            sf[nf][2] = ex2f(sf[nf][2] - mn1);
            sf[nf][3] = ex2f(sf[nf][3] - mn1);
            rs0 += sf[nf][0] + sf[nf][1];
            rs1 += sf[nf][2] + sf[nf][3];
        }
        rs0 += __shfl_xor_sync(0xffffffffu, rs0, 1);
        rs0 += __shfl_xor_sync(0xffffffffu, rs0, 2);
        rs1 += __shfl_xor_sync(0xffffffffu, rs1, 1);
        rs1 += __shfl_xor_sync(0xffffffffu, rs1, 2);

        l0 = l0 * sc0 + rs0;  m0 = mn0;
        l1 = l1 * sc1 + rs1;  m1 = mn1;
#pragma unroll
        for (int nf = 0; nf < 8; nf++) {
            o[nf][0] *= sc0;  o[nf][1] *= sc0;
            o[nf][2] *= sc1;  o[nf][3] *= sc1;
        }

        // O += P @ V : fp16 accumulator-layout identity -> A frags by packing
#pragma unroll
        for (int ks = 0; ks < 4; ks++) {
            uint32_t a0 = packh2(sf[2 * ks    ][0], sf[2 * ks    ][1]);
            uint32_t a1 = packh2(sf[2 * ks    ][2], sf[2 * ks    ][3]);
            uint32_t a2 = packh2(sf[2 * ks + 1][0], sf[2 * ks + 1][1]);
            uint32_t a3 = packh2(sf[2 * ks + 1][2], sf[2 * ks + 1][3]);
            const int klo = ks * 16 + 2 * q4;
#pragma unroll
            for (int nf = 0; nf < 8; nf++) {
                const __half* vr = VsT + (nf * 8 + g) * KVPADH + klo;
                uint32_t b0 = *(const uint32_t*)vr;
                uint32_t b1 = *(const uint32_t*)(vr + 8);
                mma16(o[nf], a0, a1, a2, a3, b0, b1);
            }
        }
        __syncthreads();
    }

    const int r0 = w * 16 + g;
    const int r1 = r0 + 8;

    if (qt < 4) {
        float inv0 = 1.f / l0, inv1 = 1.f / l1;
        float* po = gout + ((size_t)b * Tc + q0) * Hc;
#pragma unroll
        for (int nf = 0; nf < 8; nf++) {
            int col = nf * 8 + 2 * q4;
            *(float2*)(po + (size_t)r0 * Hc + col) = make_float2(o[nf][0] * inv0, o[nf][1] * inv0);
            *(float2*)(po + (size_t)r1 * Hc + col) = make_float2(o[nf][2] * inv1, o[nf][3] * inv1);
        }
    } else {
        const int slot = b * SLOTS + idx;
        float* po = g_po + (size_t)slot * 4096;
#pragma unroll
        for (int nf = 0; nf < 8; nf++) {
            int col = nf * 8 + 2 * q4;
            *(float2*)(po + r0 * 64 + col) = make_float2(o[nf][0], o[nf][1]);
            *(float2*)(po + r1 * 64 + col) = make_float2(o[nf][2], o[nf][3]);
        }
        if (q4 == 0) {
            g_pm[slot * 64 + r0] = m0;  g_pm[slot * 64 + r1] = m1;
            g_pl[slot * 64 + r0] = l0;  g_pl[slot * 64 + r1] = l1;
        }
    }
}

// ---------------------------------------------------------------------------
// Merge (unchanged from round 16: hoisted loads, deep MLP).
// ---------------------------------------------------------------------------
__global__ __launch_bounds__(256) void merge_kernel(float* __restrict__ out)
{
    const int gid  = blockIdx.x * 8 + (threadIdx.x >> 5);
    const int lane = threadIdx.x & 31;
    const int b = gid >> 11;
    const int q = gid & 2047;
    const int qt    = q >> 6;
    if (qt < 4) return;
    const int rowin = q & 63;
    const int gg    = qt >> 2;
    const int nch   = gg + 1;
    const int base  = b * SLOTS + 2 * gg * (gg + 1) + (qt - 4 * gg) * (gg + 1);
    const int col   = lane * 2;

    float  mv[8], pl[8];
    float2 ov[8];
#pragma unroll
    for (int c = 0; c < 8; c++) {
        if (c < nch) {
            mv[c] = g_pm[(base + c) * 64 + rowin];
            pl[c] = g_pl[(base + c) * 64 + rowin];
            ov[c] = *(const float2*)(g_po + ((size_t)(base + c) * 64 + rowin) * 64 + col);
        } else {
            mv[c] = -1e30f;
            pl[c] = 0.f;
            ov[c] = make_float2(0.f, 0.f);
        }
    }

    float M = mv[0];
#pragma unroll
    for (int c = 1; c < 8; c++) M = fmaxf(M, mv[c]);

    float L = 0.f, o0 = 0.f, o1 = 0.f;
#pragma unroll
    for (int c = 0; c < 8; c++) {
        float wgt = ex2f(mv[c] - M);
        L  += wgt * pl[c];
        o0 += wgt * ov[c].x;
        o1 += wgt * ov[c].y;
    }
    float inv = 1.f / L;
    *(float2*)(out + ((size_t)b * Tc + q) * Hc + col) = make_float2(o0 * inv, o1 * inv);
}

// ---------------------------------------------------------------------------
extern "C" void kernel_launch(void* const* d_in, const int* in_sizes, int n_in,
                              void* d_out, int out_size)
{
    (void)in_sizes; (void)n_in; (void)out_size;
    const float* x  = (const float*)d_in[0];
    const float* Wk = (const float*)d_in[1];
    const float* bk = (const float*)d_in[2];
    const float* Wq = (const float*)d_in[3];
    const float* bq = (const float*)d_in[4];
    const float* Wv = (const float*)d_in[5];
    const float* bv = (const float*)d_in[6];
    float* out = (float*)d_out;

    cudaFuncSetAttribute(proj_kernel, cudaFuncAttributeMaxDynamicSharedMemorySize, PSMEM);
    cudaFuncSetAttribute(attn_partial_kernel, cudaFuncAttributeMaxDynamicSharedMemorySize, ASMEM);

    prep_w_kernel<<<(3 * Hc * Dc) / 256, 256>>>(Wq, Wk, Wv);

    proj_kernel<<<(Bc * Tc) / 128, 384, PSMEM>>>(x, bq, bk, bv);

    dim3 ag(SLOTS, Bc);
    attn_partial_kernel<<<ag, 128, ASMEM>>>(out);

    merge_kernel<<<(Bc * Tc) / 8, 256>>>(out);
}